// round 11
// baseline (speedup 1.0000x reference)
#include <cuda_runtime.h>
#include <math.h>

// Shapes: x[2048,64,512], w_qkv[512,1536], out[2048,64,512]
// B=2048 windows, N=64 tokens, CH=512, H=16 heads, D=32, NW=256 mask windows.

#define LOG_SCALE_MAX 4.605170185988091f  // log(100)

// -------- scratch (device globals: allocation-free per harness rules) --------
__device__ float g_q[67108864];        // [b][h][n][d]  fp32, 256MB
__device__ float g_k[67108864];        // [b][h][n][d]
__device__ float g_v[67108864];        // [b][h][n][d]
__device__ float g_o[67108864];        // [b][n][ch]    pre-projection
__device__ float g_bias[16 * 64 * 64]; // [h][i][j] = 16*sigmoid(cpb(...))

// ============================================================================
// K0: CPB relative-position-bias table (one CTA)
// table = relu(rel_table @ w1 + b1) @ w2 ; bias[h,i,j] = 16*sigmoid(table[idx])
// ============================================================================
__global__ void cpb_kernel(const float* __restrict__ rel_table,
                           const float* __restrict__ w1,
                           const float* __restrict__ b1,
                           const float* __restrict__ w2) {
    __shared__ float tab[225][16];
    const int t = threadIdx.x;
    if (t < 225) {
        float t0 = rel_table[t * 2 + 0];
        float t1 = rel_table[t * 2 + 1];
        float acc[16];
#pragma unroll
        for (int h = 0; h < 16; ++h) acc[h] = 0.f;
        for (int j = 0; j < 512; ++j) {
            float hv = fmaf(t0, w1[j], fmaf(t1, w1[512 + j], b1[j]));
            hv = fmaxf(hv, 0.f);
#pragma unroll
            for (int h = 0; h < 16; ++h) acc[h] = fmaf(hv, w2[j * 16 + h], acc[h]);
        }
#pragma unroll
        for (int h = 0; h < 16; ++h) tab[t][h] = acc[h];
    }
    __syncthreads();
    for (int e = t; e < 16 * 64 * 64; e += blockDim.x) {
        int h = e >> 12;
        int i = (e >> 6) & 63;
        int j = e & 63;
        int dh = (i >> 3) - (j >> 3) + 7;   // 0..14
        int dw = (i & 7) - (j & 7) + 7;     // 0..14
        float v = tab[dh * 15 + dw][h];
        g_bias[e] = 16.f / (1.f + expf(-v));
    }
}

// ============================================================================
// K1/K3: fp32 SGEMM, BM=BN=128, BK=8, 256 threads, 8x8 per-thread microtile.
// MODE 0: C = X @ w_qkv + qkv_bias, scattered to g_q/g_k/g_v [b,h,n,d]
// MODE 1: C = g_o @ proj_w + proj_b, written row-major to d_out
//         (g_o is referenced DEVICE-SIDE via the symbol; passing a __device__
//          global's address from host code yields the host shadow address,
//          which HMM happily dereferences as zeros — the round-10 bug.)
// K is fixed at 512 for both.
// ============================================================================
template <int LDB, int MODE>
__global__ void __launch_bounds__(256) gemm128(
    const float* __restrict__ Ain, const float* __restrict__ B,
    const float* __restrict__ bias1, const float* __restrict__ bias2,
    float* __restrict__ outp)
{
    const float* __restrict__ A = (MODE == 1) ? (const float*)g_o : Ain;

    __shared__ float As[8][128];   // transposed: As[k][m]
    __shared__ float Bs[8][128];   // Bs[k][n]

    const int tid  = threadIdx.x;
    const int m0   = blockIdx.y * 128;
    const int n0   = blockIdx.x * 128;
    const int trow = tid >> 4;     // 0..15
    const int tcol = tid & 15;     // 0..15

    float acc[8][8];
#pragma unroll
    for (int i = 0; i < 8; ++i)
#pragma unroll
        for (int j = 0; j < 8; ++j) acc[i][j] = 0.f;

    const int arow = tid >> 1;         // 0..127
    const int acol = (tid & 1) * 4;    // 0 or 4
    const int brow = tid >> 5;         // 0..7
    const int bcol = (tid & 31) * 4;   // 0..124

    for (int k0 = 0; k0 < 512; k0 += 8) {
        float4 av = *(const float4*)&A[(size_t)(m0 + arow) * 512 + k0 + acol];
        float4 bv = *(const float4*)&B[(size_t)(k0 + brow) * LDB + n0 + bcol];
        __syncthreads();
        As[acol + 0][arow] = av.x;
        As[acol + 1][arow] = av.y;
        As[acol + 2][arow] = av.z;
        As[acol + 3][arow] = av.w;
        *(float4*)&Bs[brow][bcol] = bv;
        __syncthreads();
#pragma unroll
        for (int kk = 0; kk < 8; ++kk) {
            float4 a0 = *(const float4*)&As[kk][trow * 8];
            float4 a1 = *(const float4*)&As[kk][trow * 8 + 4];
            float4 b0 = *(const float4*)&Bs[kk][tcol * 8];
            float4 b1 = *(const float4*)&Bs[kk][tcol * 8 + 4];
            float ar[8] = {a0.x, a0.y, a0.z, a0.w, a1.x, a1.y, a1.z, a1.w};
            float br[8] = {b0.x, b0.y, b0.z, b0.w, b1.x, b1.y, b1.z, b1.w};
#pragma unroll
            for (int i = 0; i < 8; ++i)
#pragma unroll
                for (int j = 0; j < 8; ++j)
                    acc[i][j] = fmaf(ar[i], br[j], acc[i][j]);
        }
    }

    const int c0 = n0 + tcol * 8;  // global output column base (multiple of 8)

    if (MODE == 0) {
        // qkv scatter: c = s*512 + h*32 + d ; 8-col chunk stays within one head
        const int s      = c0 >> 9;        // 0=q 1=k 2=v
        const int within = c0 & 511;
        const int h      = within >> 5;
        const int dd     = within & 31;
        float* dst_base  = (s == 0) ? g_q : (s == 1) ? g_k : g_v;
        float bs[8];
#pragma unroll
        for (int j = 0; j < 8; ++j)
            bs[j] = (s == 0) ? bias1[within + j]
                  : (s == 2) ? bias2[within + j] : 0.f;
#pragma unroll
        for (int i = 0; i < 8; ++i) {
            int m = m0 + trow * 8 + i;
            int b = m >> 6, n = m & 63;
            float* dst = dst_base + (((size_t)b * 16 + h) * 64 + n) * 32 + dd;
            float4 o0 = make_float4(acc[i][0] + bs[0], acc[i][1] + bs[1],
                                    acc[i][2] + bs[2], acc[i][3] + bs[3]);
            float4 o1 = make_float4(acc[i][4] + bs[4], acc[i][5] + bs[5],
                                    acc[i][6] + bs[6], acc[i][7] + bs[7]);
            *(float4*)dst       = o0;
            *(float4*)(dst + 4) = o1;
        }
    } else {
        float bs[8];
#pragma unroll
        for (int j = 0; j < 8; ++j) bs[j] = bias1[c0 + j];
#pragma unroll
        for (int i = 0; i < 8; ++i) {
            int m = m0 + trow * 8 + i;
            float* dst = outp + (size_t)m * 512 + c0;
            float4 o0 = make_float4(acc[i][0] + bs[0], acc[i][1] + bs[1],
                                    acc[i][2] + bs[2], acc[i][3] + bs[3]);
            float4 o1 = make_float4(acc[i][4] + bs[4], acc[i][5] + bs[5],
                                    acc[i][6] + bs[6], acc[i][7] + bs[7]);
            *(float4*)dst       = o0;
            *(float4*)(dst + 4) = o1;
        }
    }
}

// ============================================================================
// K2: fused attention per (window b, head h). 128 threads.
// qn = q/||q|| * exp(min(logit_scale,LOG_SCALE_MAX)); kn = k/||k||
// S = qn knT + bias[h] + mask[b%256]; softmax rows; O = P V -> g_o[b,n,h*32+d]
// ============================================================================
__global__ void __launch_bounds__(128) attn_kernel(
    const float* __restrict__ mask,
    const float* __restrict__ logit_scale)
{
    __shared__ float qt[32][64];   // transposed, scale folded in
    __shared__ float kt[32][64];   // transposed
    __shared__ float vv[64][32];
    __shared__ float Ss[64][65];   // padded to 65 to avoid bank conflicts in PV
    __shared__ float inv_sum[64];

    const int t = threadIdx.x;
    const int h = blockIdx.x;
    const int b = blockIdx.y;
    const size_t base = ((size_t)b * 16 + h) * 2048;

    // ---- load V (coalesced) ----
    {
        const float* vg = g_v + base;
        float* vf = (float*)vv;
#pragma unroll
        for (int idx = t; idx < 2048; idx += 128) vf[idx] = vg[idx];
    }

    // ---- load + normalize Q (threads 0..63) / K (threads 64..127), transpose ----
    if (t < 64) {
        const float* qg = g_q + base + t * 32;
        float vals[32];
        float ss = 0.f;
#pragma unroll
        for (int d4 = 0; d4 < 8; ++d4) {
            float4 v4 = *(const float4*)&qg[d4 * 4];
            vals[d4 * 4 + 0] = v4.x; vals[d4 * 4 + 1] = v4.y;
            vals[d4 * 4 + 2] = v4.z; vals[d4 * 4 + 3] = v4.w;
        }
#pragma unroll
        for (int d = 0; d < 32; ++d) ss = fmaf(vals[d], vals[d], ss);
        float scale = expf(fminf(logit_scale[t & 15], LOG_SCALE_MAX)); // any lane; h below
        scale = expf(fminf(logit_scale[h], LOG_SCALE_MAX));
        float inv = scale / sqrtf(ss);
#pragma unroll
        for (int d = 0; d < 32; ++d) qt[d][t] = vals[d] * inv;
    } else {
        const int r = t - 64;
        const float* kg = g_k + base + r * 32;
        float vals[32];
        float ss = 0.f;
#pragma unroll
        for (int d4 = 0; d4 < 8; ++d4) {
            float4 v4 = *(const float4*)&kg[d4 * 4];
            vals[d4 * 4 + 0] = v4.x; vals[d4 * 4 + 1] = v4.y;
            vals[d4 * 4 + 2] = v4.z; vals[d4 * 4 + 3] = v4.w;
        }
#pragma unroll
        for (int d = 0; d < 32; ++d) ss = fmaf(vals[d], vals[d], ss);
        float inv = 1.f / sqrtf(ss);
#pragma unroll
        for (int d = 0; d < 32; ++d) kt[d][r] = vals[d] * inv;
    }
    __syncthreads();

    // ---- S = qn knT (+bias +mask): each thread 4 rows x 8 cols ----
    {
        const int r0 = (t >> 3) * 4;   // 0..60
        const int c0 = (t & 7) * 8;    // 0..56
        float acc[4][8];
#pragma unroll
        for (int i = 0; i < 4; ++i)
#pragma unroll
            for (int j = 0; j < 8; ++j) acc[i][j] = 0.f;
#pragma unroll
        for (int kk = 0; kk < 32; ++kk) {
            float4 a  = *(const float4*)&qt[kk][r0];
            float4 b0 = *(const float4*)&kt[kk][c0];
            float4 b1 = *(const float4*)&kt[kk][c0 + 4];
            float ar[4] = {a.x, a.y, a.z, a.w};
            float br[8] = {b0.x, b0.y, b0.z, b0.w, b1.x, b1.y, b1.z, b1.w};
#pragma unroll
            for (int i = 0; i < 4; ++i)
#pragma unroll
                for (int j = 0; j < 8; ++j)
                    acc[i][j] = fmaf(ar[i], br[j], acc[i][j]);
        }
        const float* mrow = mask + (size_t)(b & 255) * 4096;
        const float* brow = g_bias + h * 4096;
#pragma unroll
        for (int i = 0; i < 4; ++i) {
            int r = r0 + i;
            float4 m0v = *(const float4*)&mrow[r * 64 + c0];
            float4 m1v = *(const float4*)&mrow[r * 64 + c0 + 4];
            float4 b0v = *(const float4*)&brow[r * 64 + c0];
            float4 b1v = *(const float4*)&brow[r * 64 + c0 + 4];
            Ss[r][c0 + 0] = acc[i][0] + m0v.x + b0v.x;
            Ss[r][c0 + 1] = acc[i][1] + m0v.y + b0v.y;
            Ss[r][c0 + 2] = acc[i][2] + m0v.z + b0v.z;
            Ss[r][c0 + 3] = acc[i][3] + m0v.w + b0v.w;
            Ss[r][c0 + 4] = acc[i][4] + m1v.x + b1v.x;
            Ss[r][c0 + 5] = acc[i][5] + m1v.y + b1v.y;
            Ss[r][c0 + 6] = acc[i][6] + m1v.z + b1v.z;
            Ss[r][c0 + 7] = acc[i][7] + m1v.w + b1v.w;
        }
    }
    __syncthreads();

    // ---- softmax: 2 threads per row (adjacent lanes, shfl_xor combine) ----
    {
        const int row = t >> 1;
        const int off = (t & 1) * 32;
        float mx = -1e30f;
#pragma unroll
        for (int j = 0; j < 32; ++j) mx = fmaxf(mx, Ss[row][off + j]);
        mx = fmaxf(mx, __shfl_xor_sync(0xffffffffu, mx, 1));
        float sm = 0.f;
#pragma unroll
        for (int j = 0; j < 32; ++j) {
            float e = expf(Ss[row][off + j] - mx);
            Ss[row][off + j] = e;
            sm += e;
        }
        sm += __shfl_xor_sync(0xffffffffu, sm, 1);
        if ((t & 1) == 0) inv_sum[row] = 1.f / sm;
    }
    __syncthreads();

    // ---- O = P V: each thread 4 rows x 4 cols ----
    {
        const int r0 = (t >> 3) * 4;   // 0..60
        const int c0 = (t & 7) * 4;    // 0..28
        float acc[4][4];
#pragma unroll
        for (int i = 0; i < 4; ++i)
#pragma unroll
            for (int j = 0; j < 4; ++j) acc[i][j] = 0.f;
#pragma unroll
        for (int kk = 0; kk < 64; ++kk) {
            float4 bv = *(const float4*)&vv[kk][c0];
#pragma unroll
            for (int i = 0; i < 4; ++i) {
                float a = Ss[r0 + i][kk];
                acc[i][0] = fmaf(a, bv.x, acc[i][0]);
                acc[i][1] = fmaf(a, bv.y, acc[i][1]);
                acc[i][2] = fmaf(a, bv.z, acc[i][2]);
                acc[i][3] = fmaf(a, bv.w, acc[i][3]);
            }
        }
#pragma unroll
        for (int i = 0; i < 4; ++i) {
            int r = r0 + i;
            float is = inv_sum[r];
            float4 o4 = make_float4(acc[i][0] * is, acc[i][1] * is,
                                    acc[i][2] * is, acc[i][3] * is);
            *(float4*)&g_o[((size_t)b * 64 + r) * 512 + h * 32 + c0] = o4;
        }
    }
}

// ============================================================================
// launch
// ============================================================================
extern "C" void kernel_launch(void* const* d_in, const int* in_sizes, int n_in,
                              void* d_out, int out_size) {
    const float* x           = (const float*)d_in[0];   // [2048,64,512]
    const float* mask        = (const float*)d_in[1];   // [256,64,64]
    const float* rel_table   = (const float*)d_in[2];   // [1,15,15,2]
    const float* w_qkv       = (const float*)d_in[3];   // [512,1536]
    const float* q_bias      = (const float*)d_in[4];   // [512]
    const float* v_bias      = (const float*)d_in[5];   // [512]
    const float* logit_scale = (const float*)d_in[6];   // [16]
    const float* cpb_w1      = (const float*)d_in[7];   // [2,512]
    const float* cpb_b1      = (const float*)d_in[8];   // [512]
    const float* cpb_w2      = (const float*)d_in[9];   // [512,16]
    const float* proj_w      = (const float*)d_in[10];  // [512,512]
    const float* proj_b      = (const float*)d_in[11];  // [512]
    float* out = (float*)d_out;                          // [2048,64,512]

    // K0: CPB bias table (tiny)
    cpb_kernel<<<1, 256>>>(rel_table, cpb_w1, cpb_b1, cpb_w2);

    // K1: QKV GEMM + bias + scatter to [b,h,n,d]
    gemm128<1536, 0><<<dim3(12, 1024), 256>>>(x, w_qkv, q_bias, v_bias, nullptr);

    // K2: fused window attention per (head, window)
    attn_kernel<<<dim3(16, 2048), 128>>>(mask, logit_scale);

    // K3: output projection + bias (reads g_o device-side; Ain ignored)
    gemm128<512, 1><<<dim3(4, 1024), 256>>>(nullptr, proj_w, proj_b, nullptr, out);
}